// round 1
// baseline (speedup 1.0000x reference)
#include <cuda_runtime.h>

#define NQ   2048
#define NB   8192
#define DIM  32
#define QT   16            // queries per CTA
#define BSPLIT 4           // background splits
#define NBP  (NB / BSPLIT) // 2048 backgrounds per CTA
#define TPB  256

// ---- device scratch (no allocations allowed) ----
__device__ float g_xqw[NQ * DIM];   // x_query * w
__device__ float g_q2 [NQ];         // ||xq*w||^2
__device__ float g_xbw[NB * DIM];   // x_backgnd * w
__device__ float g_b2 [NB];         // ||xb*w||^2
__device__ float g_pk [NQ * BSPLIT];
__device__ float g_pky[NQ * BSPLIT];
__device__ float g_c  [2];          // c1 = -log2e/sigma, c2 = r_scale*log2e

// ---- packed f32x2 helpers (sm_103a FFMA2 path) ----
__device__ __forceinline__ unsigned long long fma2(unsigned long long a,
                                                   unsigned long long b,
                                                   unsigned long long c) {
    unsigned long long d;
    asm("fma.rn.f32x2 %0, %1, %2, %3;" : "=l"(d) : "l"(a), "l"(b), "l"(c));
    return d;
}
__device__ __forceinline__ void unpack2(unsigned long long u, float& lo, float& hi) {
    asm("mov.b64 {%0, %1}, %2;" : "=f"(lo), "=f"(hi) : "l"(u));
}
__device__ __forceinline__ unsigned long long pack2(float lo, float hi) {
    unsigned long long u;
    asm("mov.b64 %0, {%1, %2};" : "=l"(u) : "f"(lo), "f"(hi));
    return u;
}
__device__ __forceinline__ float ex2_approx(float x) {
    float y; asm("ex2.approx.ftz.f32 %0, %1;" : "=f"(y) : "f"(x)); return y;
}
__device__ __forceinline__ float rsqrt_approx(float x) {
    float y; asm("rsqrt.approx.f32 %0, %1;" : "=f"(y) : "f"(x)); return y;
}

// ---- kernel 0: scale rows by w, compute squared norms, fold constants ----
__global__ void prep_kernel(const float* __restrict__ xb,
                            const float* __restrict__ xq,
                            const float* __restrict__ w,
                            const float* __restrict__ sigma,
                            const float* __restrict__ rscale) {
    int row = blockIdx.x * blockDim.x + threadIdx.x;
    if (row == 0) {
        const float LOG2E = 1.4426950408889634f;
        g_c[0] = -LOG2E / sigma[0];
        g_c[1] = rscale[0] * LOG2E;
    }
    if (row >= NQ + NB) return;
    const float* src;
    float* dst;
    if (row < NB) { src = xb + (size_t)row * DIM; dst = g_xbw + (size_t)row * DIM; }
    else          { int q = row - NB; src = xq + (size_t)q * DIM; dst = g_xqw + (size_t)q * DIM; }
    float s = 0.f;
#pragma unroll
    for (int k = 0; k < DIM; k++) {
        float v = src[k] * w[k];
        dst[k] = v;
        s = fmaf(v, v, s);
    }
    if (row < NB) g_b2[row] = s;
    else          g_q2[row - NB] = s;
}

// ---- kernel 1: main fused distance/exp/weighted-sum ----
__global__ void __launch_bounds__(TPB)
main_kernel(const float* __restrict__ r, const float* __restrict__ yb_g) {
    __shared__ unsigned long long xq_s[QT][DIM / 2];   // packed query tile
    __shared__ float q2_s[QT];
    __shared__ float red[TPB / 32][QT][2];

    const int tid = threadIdx.x;
    const int q0  = blockIdx.x * QT;
    const int b0  = blockIdx.y * NBP;

    {   // cooperative load of 16 queries (packed f32x2), one ull per thread
        int j = tid >> 4, k = tid & 15;
        xq_s[j][k] = reinterpret_cast<const unsigned long long*>(g_xqw)[(size_t)(q0 + j) * (DIM / 2) + k];
        if (tid < QT) q2_s[tid] = g_q2[q0 + tid];
    }
    const float c1 = g_c[0], c2 = g_c[1];
    __syncthreads();

    float sum[QT], sumy[QT];
#pragma unroll
    for (int j = 0; j < QT; j++) { sum[j] = 0.f; sumy[j] = 0.f; }

    // each thread owns one background per step; xb lives in registers,
    // xq comes from SMEM as warp-wide broadcast (conflict-free)
    for (int b = b0 + tid; b < b0 + NBP; b += TPB) {
        unsigned long long xb[DIM / 2];
        const float4* xbp = reinterpret_cast<const float4*>(g_xbw + (size_t)b * DIM);
#pragma unroll
        for (int k4 = 0; k4 < DIM / 4; k4++) {
            float4 v = xbp[k4];
            xb[k4 * 2]     = pack2(v.x, v.y);
            xb[k4 * 2 + 1] = pack2(v.z, v.w);
        }
        const float b2v = g_b2[b];
        const float ybv = __ldg(yb_g + b);

#pragma unroll
        for (int j = 0; j < QT; j++) {
            unsigned long long acc = 0ull;   // bit pattern of (0.f, 0.f)
#pragma unroll
            for (int k = 0; k < DIM / 2; k++)
                acc = fma2(xq_s[j][k], xb[k], acc);
            float alo, ahi; unpack2(acc, alo, ahi);
            float dot = alo + ahi;
            float d2  = q2_s[j] + b2v - 2.f * dot;
            float rsv = rsqrt_approx(d2);
            float d   = (d2 > 0.f) ? d2 * rsv : 0.f;         // sqrt(max(d2,0))
            float rv  = __ldcs(r + (size_t)(q0 + j) * NB + b); // streaming: 64MB, read once
            float t   = fmaf(d, c1, rv * c2);                 // (-d/sigma + rs*r)*log2e
            float kv  = ex2_approx(t);
            sum[j] += kv;
            sumy[j] = fmaf(kv, ybv, sumy[j]);
        }
    }

    // deterministic reduction: warp shuffle -> smem -> global partial slots
    const int lane = tid & 31, warp = tid >> 5;
#pragma unroll
    for (int j = 0; j < QT; j++) {
#pragma unroll
        for (int o = 16; o > 0; o >>= 1) {
            sum[j]  += __shfl_xor_sync(0xffffffffu, sum[j],  o);
            sumy[j] += __shfl_xor_sync(0xffffffffu, sumy[j], o);
        }
        if (lane == 0) { red[warp][j][0] = sum[j]; red[warp][j][1] = sumy[j]; }
    }
    __syncthreads();
    if (tid < QT) {
        float sk = 0.f, sy = 0.f;
#pragma unroll
        for (int wi = 0; wi < TPB / 32; wi++) { sk += red[wi][tid][0]; sy += red[wi][tid][1]; }
        g_pk [(q0 + tid) * BSPLIT + blockIdx.y] = sk;
        g_pky[(q0 + tid) * BSPLIT + blockIdx.y] = sy;
    }
}

// ---- kernel 2: combine splits, normalize ----
__global__ void fin_kernel(float* __restrict__ out) {
    int q = blockIdx.x * blockDim.x + threadIdx.x;
    if (q >= NQ) return;
    float sk = 0.f, sy = 0.f;
#pragma unroll
    for (int s = 0; s < BSPLIT; s++) { sk += g_pk[q * BSPLIT + s]; sy += g_pky[q * BSPLIT + s]; }
    out[q] = sy / (sk + 1e-8f);
}

extern "C" void kernel_launch(void* const* d_in, const int* in_sizes, int n_in,
                              void* d_out, int out_size) {
    const float* xb     = (const float*)d_in[0];  // (8192, 32)
    const float* yb     = (const float*)d_in[1];  // (8192,)
    const float* xq     = (const float*)d_in[2];  // (2048, 32)
    const float* r      = (const float*)d_in[3];  // (2048, 8192)
    const float* sigma  = (const float*)d_in[4];
    const float* rscale = (const float*)d_in[5];
    const float* w      = (const float*)d_in[6];
    float* out = (float*)d_out;

    prep_kernel<<<(NQ + NB + TPB - 1) / TPB, TPB>>>(xb, xq, w, sigma, rscale);
    dim3 grid(NQ / QT, BSPLIT);
    main_kernel<<<grid, TPB>>>(r, yb);
    fin_kernel<<<(NQ + TPB - 1) / TPB, TPB>>>(out);
}

// round 4
// speedup vs baseline: 2.4297x; 2.4297x over previous
#include <cuda_runtime.h>
#include <cuda_bf16.h>
#include <cstdint>

#define NQ 2048
#define NB 8192
#define DIM 32
#define K96 96
#define TPB 256
#define QPC 256            // queries per CTA
#define BSPL 16            // background splits (grid.y)
#define BPC (NB / BSPL)    // 512 backgrounds per CTA
#define NSUB (BPC / 8)     // 64 subtiles of 8 backgrounds
#define STRIDE 208         // SMEM row stride bytes (13*16 -> conflict-free ldmatrix)

// ---------------- device scratch ----------------
__device__ __align__(16) __nv_bfloat16 g_A[NQ * K96];  // queries  [qhi|qlo|qhi]
__device__ __align__(16) __nv_bfloat16 g_B[NB * K96];  // backgnds [bhi|bhi|blo]
__device__ float g_q2[NQ];
__device__ float g_b2[NB];
__device__ float g_pk [NQ * BSPL];
__device__ float g_pky[NQ * BSPL];
__device__ float g_c[2];   // c1 = -log2e/sigma, c2 = r_scale*log2e

// ---------------- helpers ----------------
__device__ __forceinline__ uint32_t smem_u32(const void* p) {
    uint32_t a;
    asm("{ .reg .u64 t; cvta.to.shared.u64 t, %1; cvt.u32.u64 %0, t; }" : "=r"(a) : "l"(p));
    return a;
}
__device__ __forceinline__ void ldsm_x4(uint32_t* r, uint32_t addr) {
    asm volatile("ldmatrix.sync.aligned.m8n8.x4.shared.b16 {%0,%1,%2,%3}, [%4];"
                 : "=r"(r[0]), "=r"(r[1]), "=r"(r[2]), "=r"(r[3]) : "r"(addr));
}
__device__ __forceinline__ void ldsm_x2(uint32_t* r, uint32_t addr) {
    asm volatile("ldmatrix.sync.aligned.m8n8.x2.shared.b16 {%0,%1}, [%2];"
                 : "=r"(r[0]), "=r"(r[1]) : "r"(addr));
}
__device__ __forceinline__ void mma_bf16(float* d, const uint32_t* a, const uint32_t* b) {
    asm volatile(
        "mma.sync.aligned.m16n8k16.row.col.f32.bf16.bf16.f32 "
        "{%0,%1,%2,%3}, {%4,%5,%6,%7}, {%8,%9}, {%0,%1,%2,%3};"
        : "+f"(d[0]), "+f"(d[1]), "+f"(d[2]), "+f"(d[3])
        : "r"(a[0]), "r"(a[1]), "r"(a[2]), "r"(a[3]), "r"(b[0]), "r"(b[1]));
}
__device__ __forceinline__ float ex2a(float x) {
    float y; asm("ex2.approx.ftz.f32 %0, %1;" : "=f"(y) : "f"(x)); return y;
}
__device__ __forceinline__ float sqrta(float x) {
    float y; asm("sqrt.approx.f32 %0, %1;" : "=f"(y) : "f"(x)); return y;
}
__device__ __forceinline__ void cp16(uint32_t sdst, const void* gsrc) {
    asm volatile("cp.async.cg.shared.global [%0], [%1], 16;" :: "r"(sdst), "l"(gsrc));
}

// ---------------- SMEM layout ----------------
#define SM_A  0
#define SM_B  (QPC * STRIDE)                 // 53248
#define SM_B2 (SM_B + BPC * STRIDE)          // 159744
#define SM_YB (SM_B2 + BPC * 4)              // 161792
#define SMEM_TOTAL (SM_YB + BPC * 4)         // 163840

// ---------------- kernel 0: prep ----------------
__global__ void prep_kernel(const float* __restrict__ xb,
                            const float* __restrict__ xq,
                            const float* __restrict__ w,
                            const float* __restrict__ sigma,
                            const float* __restrict__ rscale) {
    if (blockIdx.x == 0 && threadIdx.x == 0) {
        const float LOG2E = 1.4426950408889634f;
        g_c[0] = -LOG2E / sigma[0];
        g_c[1] = rscale[0] * LOG2E;
    }
    int warp = (blockIdx.x * blockDim.x + threadIdx.x) >> 5;
    int lane = threadIdx.x & 31;
    if (warp >= NB + NQ) return;
    const float* src = (warp < NB) ? (xb + (size_t)warp * DIM)
                                   : (xq + (size_t)(warp - NB) * DIM);
    float v = src[lane] * w[lane];
    float s = v * v;
#pragma unroll
    for (int o = 16; o > 0; o >>= 1) s += __shfl_xor_sync(0xffffffffu, s, o);
    __nv_bfloat16 hi = __float2bfloat16(v);
    __nv_bfloat16 lo = __float2bfloat16(v - __bfloat162float(hi));
    if (warp < NB) {                       // background: [hi | hi | lo]
        __nv_bfloat16* d = g_B + (size_t)warp * K96;
        d[lane] = hi; d[32 + lane] = hi; d[64 + lane] = lo;
        if (lane == 0) g_b2[warp] = s;
    } else {                               // query: [hi | lo | hi]
        int q = warp - NB;
        __nv_bfloat16* d = g_A + (size_t)q * K96;
        d[lane] = hi; d[32 + lane] = lo; d[64 + lane] = hi;
        if (lane == 0) g_q2[q] = s;
    }
}

// ---------------- kernel 1: HMMA GEMM + fused epilogue ----------------
__global__ void __launch_bounds__(TPB, 1)
main_kernel(const float* __restrict__ r, const float* __restrict__ yb) {
    extern __shared__ char smem[];
    const uint32_t sbase = smem_u32(smem);
    const int tid = threadIdx.x, wid = tid >> 5, lane = tid & 31;
    const int q0 = blockIdx.x * QPC;
    const int b0 = blockIdx.y * BPC;
    const int qw = wid * 32;               // this warp's query offset within CTA

    // ---- stage A (256 q), B (512 b), b2, yb into SMEM ----
#pragma unroll
    for (int i = 0; i < 12; ++i) {         // A: 3072 16B chunks
        int ch = tid + i * TPB;
        int row = ch / 12, c = ch % 12;
        cp16(sbase + SM_A + row * STRIDE + c * 16,
             (const char*)(g_A + (size_t)(q0 + row) * K96) + c * 16);
    }
#pragma unroll
    for (int i = 0; i < 24; ++i) {         // B: 6144 16B chunks
        int ch = tid + i * TPB;
        int row = ch / 12, c = ch % 12;
        cp16(sbase + SM_B + row * STRIDE + c * 16,
             (const char*)(g_B + (size_t)(b0 + row) * K96) + c * 16);
    }
    if (tid < 128) {
        cp16(sbase + SM_B2 + tid * 16, (const char*)(g_b2 + b0) + tid * 16);
        cp16(sbase + SM_YB + tid * 16, (const char*)(yb + b0) + tid * 16);
    }
    asm volatile("cp.async.commit_group;" ::: "memory");
    asm volatile("cp.async.wait_group 0;" ::: "memory");
    __syncthreads();

    // ---- A fragments (register resident): 2 m-tiles x 6 k-chunks x 4 regs ----
    uint32_t afr[2][6][4];
    {
        int arow = (lane & 7) + ((lane >> 3) & 1) * 8;
        int akof = (lane >> 4) * 16;
#pragma unroll
        for (int mt = 0; mt < 2; ++mt)
#pragma unroll
            for (int c = 0; c < 6; ++c)
                ldsm_x4(afr[mt][c],
                        sbase + SM_A + (qw + mt * 16 + arow) * STRIDE + c * 32 + akof);
    }
    const uint32_t b_lane = sbase + SM_B + (lane & 7) * STRIDE + ((lane >> 3) & 1) * 16;

    const float c1 = g_c[0], c2 = g_c[1];
    float q2v[4];
#pragma unroll
    for (int i = 0; i < 4; ++i)            // i = mt*2 + rh
        q2v[i] = g_q2[q0 + qw + (i >> 1) * 16 + (i & 1) * 8 + (lane >> 2)];

    // per-thread r base: row = qw + lane/4, col = (lane&3)*2
    const float* rbase = r + (size_t)(q0 + qw + (lane >> 2)) * NB + b0 + (lane & 3) * 2;

    float sk[4] = {0.f, 0.f, 0.f, 0.f}, sky[4] = {0.f, 0.f, 0.f, 0.f};
    float rpf[2][8];

    // prefetch r for subtiles 0,1
#pragma unroll
    for (int s = 0; s < 2; ++s)
#pragma unroll
        for (int i = 0; i < 8; ++i)        // i = mt*4 + rh*2 + j
            rpf[s][i] = __ldcs(rbase + (size_t)s * 8 +
                               ((i >> 2) * 16 + ((i >> 1) & 1) * 8) * (size_t)NB + (i & 1));

#pragma unroll 2
    for (int s = 0; s < NSUB; ++s) {
        // B fragments for 8 backgrounds
        uint32_t bfr[6][2];
#pragma unroll
        for (int c = 0; c < 6; ++c)
            ldsm_x2(bfr[c], b_lane + s * (8 * STRIDE) + c * 32);

        float acc[2][4] = {{0.f, 0.f, 0.f, 0.f}, {0.f, 0.f, 0.f, 0.f}};
#pragma unroll
        for (int c = 0; c < 6; ++c) {
            mma_bf16(acc[0], afr[0][c], bfr[c]);
            mma_bf16(acc[1], afr[1][c], bfr[c]);
        }

        // snapshot current subtile's r BEFORE overwriting the buffer slot
        float rcur[8];
#pragma unroll
        for (int i = 0; i < 8; ++i) rcur[i] = rpf[s & 1][i];

        // prefetch r for subtile s+2 (into the slot we just drained)
        if (s + 2 < NSUB) {
#pragma unroll
            for (int i = 0; i < 8; ++i)
                rpf[s & 1][i] = __ldcs(rbase + (size_t)(s + 2) * 8 +
                                       ((i >> 2) * 16 + ((i >> 1) & 1) * 8) * (size_t)NB + (i & 1));
        }

        // b2 / yb for this thread's two columns
        float2 b2p = *(const float2*)(smem + SM_B2 + (s * 8 + (lane & 3) * 2) * 4);
        float2 ybp = *(const float2*)(smem + SM_YB + (s * 8 + (lane & 3) * 2) * 4);
        const float b2a[2] = {b2p.x, b2p.y};
        const float yba[2] = {ybp.x, ybp.y};

#pragma unroll
        for (int i = 0; i < 8; ++i) {      // i = mt*4 + rh*2 + j
            int mt = i >> 2, rh = (i >> 1) & 1, j = i & 1;
            float dot = acc[mt][rh * 2 + j];
            float d2  = fmaxf(fmaf(-2.f, dot, q2v[mt * 2 + rh] + b2a[j]), 0.f);
            float d   = sqrta(d2);
            float tt  = fmaf(d, c1, rcur[i] * c2);
            float kv  = ex2a(tt);
            sk [mt * 2 + rh] += kv;
            sky[mt * 2 + rh] = fmaf(kv, yba[j], sky[mt * 2 + rh]);
        }
    }

    // quad reduction (cols live on lanes t%4) -> lane%4==0 holds q-row sums
#pragma unroll
    for (int i = 0; i < 4; ++i) {
        sk [i] += __shfl_xor_sync(0xffffffffu, sk [i], 1);
        sk [i] += __shfl_xor_sync(0xffffffffu, sk [i], 2);
        sky[i] += __shfl_xor_sync(0xffffffffu, sky[i], 1);
        sky[i] += __shfl_xor_sync(0xffffffffu, sky[i], 2);
    }
    if ((lane & 3) == 0) {
#pragma unroll
        for (int i = 0; i < 4; ++i) {
            int q = q0 + qw + (i >> 1) * 16 + (i & 1) * 8 + (lane >> 2);
            g_pk [q * BSPL + blockIdx.y] = sk[i];
            g_pky[q * BSPL + blockIdx.y] = sky[i];
        }
    }
}

// ---------------- kernel 2: finalize ----------------
__global__ void fin_kernel(float* __restrict__ out) {
    int q = blockIdx.x * blockDim.x + threadIdx.x;
    if (q >= NQ) return;
    float skv = 0.f, syv = 0.f;
#pragma unroll
    for (int s = 0; s < BSPL; ++s) {
        skv += g_pk [q * BSPL + s];
        syv += g_pky[q * BSPL + s];
    }
    out[q] = syv / (skv + 1e-8f);
}

extern "C" void kernel_launch(void* const* d_in, const int* in_sizes, int n_in,
                              void* d_out, int out_size) {
    const float* xb     = (const float*)d_in[0];
    const float* yb     = (const float*)d_in[1];
    const float* xq     = (const float*)d_in[2];
    const float* r      = (const float*)d_in[3];
    const float* sigma  = (const float*)d_in[4];
    const float* rscale = (const float*)d_in[5];
    const float* w      = (const float*)d_in[6];
    float* out = (float*)d_out;

    cudaFuncSetAttribute(main_kernel, cudaFuncAttributeMaxDynamicSharedMemorySize, SMEM_TOTAL);

    prep_kernel<<<(NB + NQ) * 32 / TPB, TPB>>>(xb, xq, w, sigma, rscale);
    dim3 grid(NQ / QPC, BSPL);
    main_kernel<<<grid, TPB, SMEM_TOTAL>>>(r, yb);
    fin_kernel<<<(NQ + 255) / 256, 256>>>(out);
}

// round 5
// speedup vs baseline: 2.5402x; 1.0455x over previous
#include <cuda_runtime.h>
#include <cuda_bf16.h>
#include <cstdint>

#define NQ 2048
#define NB 8192
#define DIM 32
#define K96 96
#define TPB 256
#define QPC 256            // queries per CTA
#define BSPL 16            // background splits (grid.y)
#define BPC (NB / BSPL)    // 512 backgrounds per CTA
#define GW  32             // group width in b
#define NGRP (BPC / GW)    // 16 groups
#define STRIDE 208         // SMEM row stride bytes (13*16 -> conflict-free ldmatrix)
#define DSTR 34            // dot buffer stride (floats): aligned STS.64, conflict-free LDS

// ---------------- device scratch ----------------
__device__ __align__(16) __nv_bfloat16 g_A[NQ * K96];  // queries  [qhi|qlo|qhi]
__device__ __align__(16) __nv_bfloat16 g_B[NB * K96];  // backgnds [bhi|bhi|blo]
__device__ float g_q2[NQ];
__device__ float g_b2[NB];
__device__ float g_pk [NQ * BSPL];
__device__ float g_pky[NQ * BSPL];
__device__ float g_c[2];   // c1 = -log2e/sigma, c2 = r_scale*log2e

// ---------------- helpers ----------------
__device__ __forceinline__ uint32_t smem_u32(const void* p) {
    uint32_t a;
    asm("{ .reg .u64 t; cvta.to.shared.u64 t, %1; cvt.u32.u64 %0, t; }" : "=r"(a) : "l"(p));
    return a;
}
__device__ __forceinline__ void ldsm_x4(uint32_t* r, uint32_t addr) {
    asm volatile("ldmatrix.sync.aligned.m8n8.x4.shared.b16 {%0,%1,%2,%3}, [%4];"
                 : "=r"(r[0]), "=r"(r[1]), "=r"(r[2]), "=r"(r[3]) : "r"(addr));
}
__device__ __forceinline__ void mma_bf16(float* d, const uint32_t* a, const uint32_t* b) {
    asm volatile(
        "mma.sync.aligned.m16n8k16.row.col.f32.bf16.bf16.f32 "
        "{%0,%1,%2,%3}, {%4,%5,%6,%7}, {%8,%9}, {%0,%1,%2,%3};"
        : "+f"(d[0]), "+f"(d[1]), "+f"(d[2]), "+f"(d[3])
        : "r"(a[0]), "r"(a[1]), "r"(a[2]), "r"(a[3]), "r"(b[0]), "r"(b[1]));
}
__device__ __forceinline__ float ex2a(float x) {
    float y; asm("ex2.approx.ftz.f32 %0, %1;" : "=f"(y) : "f"(x)); return y;
}
__device__ __forceinline__ float sqrta(float x) {
    float y; asm("sqrt.approx.f32 %0, %1;" : "=f"(y) : "f"(x)); return y;
}
__device__ __forceinline__ void cp16(uint32_t sdst, const void* gsrc) {
    asm volatile("cp.async.cg.shared.global [%0], [%1], 16;" :: "r"(sdst), "l"(gsrc));
}

// transpose-reduce 16 regs over 32 lanes; lane L ends holding total for idx (L>>1)&15
__device__ __forceinline__ float treduce16(float* v, int lane) {
#pragma unroll
    for (int o = 16; o >= 2; o >>= 1) {
        bool up = (lane & o) != 0;
#pragma unroll
        for (int j = 0; j < 16; ++j) {
            if (j < (o >> 1)) {
                float send = up ? v[j] : v[j + (o >> 1)];
                float recv = __shfl_xor_sync(0xffffffffu, send, o);
                float keep = up ? v[j + (o >> 1)] : v[j];
                v[j] = keep + recv;
            }
        }
    }
    return v[0] + __shfl_xor_sync(0xffffffffu, v[0], 1);
}

// ---------------- SMEM layout ----------------
#define SM_A   0
#define SM_B   (QPC * STRIDE)                 // 53248
#define SM_DOT (SM_B + BPC * STRIDE)          // 159744
#define DOTSZ  (32 * DSTR * 4)                // 4352 bytes per warp
#define SM_B2  (SM_DOT + 8 * DOTSZ)           // 194560
#define SM_YB  (SM_B2 + BPC * 4)              // 196608
#define SM_Q2  (SM_YB + BPC * 4)              // 198656
#define SMEM_TOTAL (SM_Q2 + QPC * 4)          // 199680

// ---------------- kernel 0: prep (8 rows per warp, batched) ----------------
__global__ void prep_kernel(const float* __restrict__ xb,
                            const float* __restrict__ xq,
                            const float* __restrict__ w,
                            const float* __restrict__ sigma,
                            const float* __restrict__ rscale) {
    if (blockIdx.x == 0 && threadIdx.x == 0) {
        const float LOG2E = 1.4426950408889634f;
        g_c[0] = -LOG2E / sigma[0];
        g_c[1] = rscale[0] * LOG2E;
    }
    int gw = (blockIdx.x * blockDim.x + threadIdx.x) >> 5;   // global warp
    int lane = threadIdx.x & 31;
    int base = gw * 8;                                       // first row of 8
    if (base >= NB + NQ) return;
    const float wv = w[lane];
    bool isB = base < NB;                                    // 8192/8 aligns: no straddle
    const float* src = isB ? (xb + (size_t)base * DIM)
                           : (xq + (size_t)(base - NB) * DIM);
    float v[8];
#pragma unroll
    for (int j = 0; j < 8; ++j) v[j] = __ldg(src + j * DIM + lane) * wv;
#pragma unroll
    for (int j = 0; j < 8; ++j) {
        int row = base + j;
        float s = v[j] * v[j];
#pragma unroll
        for (int o = 16; o > 0; o >>= 1) s += __shfl_xor_sync(0xffffffffu, s, o);
        __nv_bfloat16 hi = __float2bfloat16(v[j]);
        __nv_bfloat16 lo = __float2bfloat16(v[j] - __bfloat162float(hi));
        if (isB) {                         // background: [hi | hi | lo]
            __nv_bfloat16* d = g_B + (size_t)row * K96;
            d[lane] = hi; d[32 + lane] = hi; d[64 + lane] = lo;
            if (lane == 0) g_b2[row] = s;
        } else {                           // query: [hi | lo | hi]
            int q = row - NB;
            __nv_bfloat16* d = g_A + (size_t)q * K96;
            d[lane] = hi; d[32 + lane] = lo; d[64 + lane] = hi;
            if (lane == 0) g_q2[q] = s;
        }
    }
}

// ---------------- kernel 1: HMMA GEMM + dot-transpose epilogue ----------------
__global__ void __launch_bounds__(TPB, 1)
main_kernel(const float* __restrict__ r, const float* __restrict__ yb) {
    extern __shared__ char smem[];
    const uint32_t sbase = smem_u32(smem);
    const int tid = threadIdx.x, wid = tid >> 5, lane = tid & 31;
    const int q0 = blockIdx.x * QPC;
    const int b0 = blockIdx.y * BPC;
    const int qw = wid * 32;               // this warp's query offset within CTA

    // ---- stage A, B, b2, yb, q2 into SMEM ----
#pragma unroll
    for (int i = 0; i < 12; ++i) {         // A: 3072 16B chunks
        int ch = tid + i * TPB;
        int row = ch / 12, c = ch % 12;
        cp16(sbase + SM_A + row * STRIDE + c * 16,
             (const char*)(g_A + (size_t)(q0 + row) * K96) + c * 16);
    }
#pragma unroll
    for (int i = 0; i < 24; ++i) {         // B: 6144 16B chunks
        int ch = tid + i * TPB;
        int row = ch / 12, c = ch % 12;
        cp16(sbase + SM_B + row * STRIDE + c * 16,
             (const char*)(g_B + (size_t)(b0 + row) * K96) + c * 16);
    }
    if (tid < 128) {
        cp16(sbase + SM_B2 + tid * 16, (const char*)(g_b2 + b0) + tid * 16);
        cp16(sbase + SM_YB + tid * 16, (const char*)(yb + b0) + tid * 16);
    }
    if (tid < 64)
        cp16(sbase + SM_Q2 + tid * 16, (const char*)(g_q2 + q0) + tid * 16);
    asm volatile("cp.async.commit_group;" ::: "memory");
    asm volatile("cp.async.wait_group 0;" ::: "memory");
    __syncthreads();

    // ---- A fragments (register resident): 2 m-tiles x 6 k-chunks x 4 regs ----
    uint32_t afr[2][6][4];
    {
        int arow = (lane & 7) + ((lane >> 3) & 1) * 8;
        int akof = (lane >> 4) * 16;
#pragma unroll
        for (int mt = 0; mt < 2; ++mt)
#pragma unroll
            for (int c = 0; c < 6; ++c)
                ldsm_x4(afr[mt][c],
                        sbase + SM_A + (qw + mt * 16 + arow) * STRIDE + c * 32 + akof);
    }
    // B ldsm.x4 lane address: matrices in order (nt0,k0),(nt0,k1),(nt1,k0),(nt1,k1)
    const int lg = lane >> 3;
    const int bsub = ((lg >> 1) << 3) + (lane & 7);     // row within 16-row pair
    const int bkh  = (lg & 1) << 4;                     // k-half byte offset
    const uint32_t bA = sbase + SM_B + bsub * STRIDE + bkh;       // n-tiles 0,1
    const uint32_t bB = bA + 16 * STRIDE;                          // n-tiles 2,3

    float* db = (float*)(smem + SM_DOT + wid * DOTSZ);
    const float* b2s = (const float*)(smem + SM_B2);
    const float* ybs = (const float*)(smem + SM_YB);
    const float* q2s = (const float*)(smem + SM_Q2);
    const float c1 = g_c[0], c2 = g_c[1];
    const float* rwarp = r + (size_t)(q0 + qw) * NB + b0;

    float accK[2] = {0.f, 0.f}, accY[2] = {0.f, 0.f};

    for (int s = 0; s < NGRP; ++s) {
        // ---- MMA: 32 b x 32 q per warp ----
        float acc[2][4][4];
#pragma unroll
        for (int mt = 0; mt < 2; ++mt)
#pragma unroll
            for (int nt = 0; nt < 4; ++nt)
#pragma unroll
                for (int k = 0; k < 4; ++k) acc[mt][nt][k] = 0.f;
#pragma unroll
        for (int c = 0; c < 6; ++c) {
            uint32_t b01[4], b23[4];
            ldsm_x4(b01, bA + s * (GW * STRIDE) + c * 32);
            ldsm_x4(b23, bB + s * (GW * STRIDE) + c * 32);
#pragma unroll
            for (int mt = 0; mt < 2; ++mt) {
                mma_bf16(acc[mt][0], afr[mt][c], b01 + 0);
                mma_bf16(acc[mt][1], afr[mt][c], b01 + 2);
                mma_bf16(acc[mt][2], afr[mt][c], b23 + 0);
                mma_bf16(acc[mt][3], afr[mt][c], b23 + 2);
            }
        }

        // ---- write dots to warp-private SMEM [q][b], stride DSTR ----
        {
            int row = (lane >> 2);
            int col = (lane & 3) * 2;
#pragma unroll
            for (int mt = 0; mt < 2; ++mt)
#pragma unroll
                for (int nt = 0; nt < 4; ++nt) {
                    int rr = mt * 16 + row, cc = nt * 8 + col;
                    *(float2*)(db + rr * DSTR + cc) =
                        make_float2(acc[mt][nt][0], acc[mt][nt][1]);
                    *(float2*)(db + (rr + 8) * DSTR + cc) =
                        make_float2(acc[mt][nt][2], acc[mt][nt][3]);
                }
        }
        __syncwarp();

        // ---- epilogue: lane = b column; r loads fully coalesced ----
        const float b2v = b2s[s * GW + lane];
        const float ybv = ybs[s * GW + lane];
#pragma unroll
        for (int h = 0; h < 2; ++h) {
            float rv[16];
#pragma unroll
            for (int i = 0; i < 16; ++i)
                rv[i] = __ldcs(rwarp + (size_t)(h * 16 + i) * NB + s * GW + lane);
            float kv[16], ky[16];
#pragma unroll
            for (int i = 0; i < 16; ++i) {
                float dot = db[(h * 16 + i) * DSTR + lane];
                float q2i = q2s[qw + h * 16 + i];
                float d2  = fmaxf(fmaf(-2.f, dot, q2i + b2v), 0.f);
                float d   = sqrta(d2);
                float kvv = ex2a(fmaf(d, c1, rv[i] * c2));
                kv[i] = kvv;
                ky[i] = kvv * ybv;
            }
            accK[h] += treduce16(kv, lane);
            accY[h] += treduce16(ky, lane);
        }
        __syncwarp();    // protect dot buffer from next group's STS
    }

    // lane L (even) holds totals for q = qw + h*16 + (L>>1)
    if (!(lane & 1)) {
#pragma unroll
        for (int h = 0; h < 2; ++h) {
            int q = q0 + qw + h * 16 + (lane >> 1);
            g_pk [q * BSPL + blockIdx.y] = accK[h];
            g_pky[q * BSPL + blockIdx.y] = accY[h];
        }
    }
}

// ---------------- kernel 2: finalize ----------------
__global__ void fin_kernel(float* __restrict__ out) {
    int q = blockIdx.x * blockDim.x + threadIdx.x;
    if (q >= NQ) return;
    float skv = 0.f, syv = 0.f;
#pragma unroll
    for (int s = 0; s < BSPL; ++s) {
        skv += g_pk [q * BSPL + s];
        syv += g_pky[q * BSPL + s];
    }
    out[q] = syv / (skv + 1e-8f);
}

extern "C" void kernel_launch(void* const* d_in, const int* in_sizes, int n_in,
                              void* d_out, int out_size) {
    const float* xb     = (const float*)d_in[0];
    const float* yb     = (const float*)d_in[1];
    const float* xq     = (const float*)d_in[2];
    const float* r      = (const float*)d_in[3];
    const float* sigma  = (const float*)d_in[4];
    const float* rscale = (const float*)d_in[5];
    const float* w      = (const float*)d_in[6];
    float* out = (float*)d_out;

    cudaFuncSetAttribute(main_kernel, cudaFuncAttributeMaxDynamicSharedMemorySize, SMEM_TOTAL);

    prep_kernel<<<(NB + NQ) / 64, TPB>>>(xb, xq, w, sigma, rscale);
    dim3 grid(NQ / QPC, BSPL);
    main_kernel<<<grid, TPB, SMEM_TOTAL>>>(r, yb);
    fin_kernel<<<(NQ + 255) / 256, 256>>>(out);
}

// round 6
// speedup vs baseline: 4.0083x; 1.5780x over previous
#include <cuda_runtime.h>
#include <cuda_bf16.h>
#include <cstdint>

#define NQ 2048
#define NB 8192
#define DIM 32
#define TPB 512
#define QPC 256            // queries per CTA
#define BSPL 16            // background splits (grid.y)
#define BPC (NB / BSPL)    // 512 backgrounds per CTA
#define GW  32             // group width in b
#define NGRP (BPC / GW)    // 16 groups
#define STRIDE 208         // SMEM row stride bytes (conflict-free ldmatrix)
#define DSTR 40            // dot buffer stride (floats)
#define LOG2E 1.4426950408889634f

// ---------------- device scratch ----------------
__device__ float g_pk [NQ * BSPL];
__device__ float g_pky[NQ * BSPL];

// ---------------- helpers ----------------
__device__ __forceinline__ uint32_t smem_u32(const void* p) {
    uint32_t a;
    asm("{ .reg .u64 t; cvta.to.shared.u64 t, %1; cvt.u32.u64 %0, t; }" : "=r"(a) : "l"(p));
    return a;
}
__device__ __forceinline__ void ldsm_x4(uint32_t* r, uint32_t addr) {
    asm volatile("ldmatrix.sync.aligned.m8n8.x4.shared.b16 {%0,%1,%2,%3}, [%4];"
                 : "=r"(r[0]), "=r"(r[1]), "=r"(r[2]), "=r"(r[3]) : "r"(addr));
}
__device__ __forceinline__ void mma_bf16(float* d, const uint32_t* a, const uint32_t* b) {
    asm volatile(
        "mma.sync.aligned.m16n8k16.row.col.f32.bf16.bf16.f32 "
        "{%0,%1,%2,%3}, {%4,%5,%6,%7}, {%8,%9}, {%0,%1,%2,%3};"
        : "+f"(d[0]), "+f"(d[1]), "+f"(d[2]), "+f"(d[3])
        : "r"(a[0]), "r"(a[1]), "r"(a[2]), "r"(a[3]), "r"(b[0]), "r"(b[1]));
}
__device__ __forceinline__ float ex2a(float x) {
    float y; asm("ex2.approx.ftz.f32 %0, %1;" : "=f"(y) : "f"(x)); return y;
}
__device__ __forceinline__ float sqrta(float x) {
    float y; asm("sqrt.approx.f32 %0, %1;" : "=f"(y) : "f"(x)); return y;
}

// transpose-reduce 16 regs over 32 lanes; lane L ends holding total for idx (L>>1)&15
__device__ __forceinline__ float treduce16(float* v, int lane) {
#pragma unroll
    for (int o = 16; o >= 2; o >>= 1) {
        bool up = (lane & o) != 0;
#pragma unroll
        for (int j = 0; j < 16; ++j) {
            if (j < (o >> 1)) {
                float send = up ? v[j] : v[j + (o >> 1)];
                float recv = __shfl_xor_sync(0xffffffffu, send, o);
                float keep = up ? v[j + (o >> 1)] : v[j];
                v[j] = keep + recv;
            }
        }
    }
    return v[0] + __shfl_xor_sync(0xffffffffu, v[0], 1);
}

// ---------------- SMEM layout ----------------
#define SM_A   0
#define SM_B   (QPC * STRIDE)                 // 53248
#define SM_DOT (SM_B + BPC * STRIDE)          // 159744
#define DOTSZ  (16 * DSTR * 4)                // 2560 bytes per warp
#define SM_B2  (SM_DOT + 16 * DOTSZ)          // 200704
#define SM_YB  (SM_B2 + BPC * 4)              // 202752
#define SM_Q2  (SM_YB + BPC * 4)              // 204800
#define SMEM_TOTAL (SM_Q2 + QPC * 4)          // 205824

// convert 8 floats to hi/lo bf16 packs (4 uint32 each)
__device__ __forceinline__ void cvt8(const float* v, uint32_t* hi, uint32_t* lo) {
#pragma unroll
    for (int j = 0; j < 4; ++j) {
        float2 p = make_float2(v[2 * j], v[2 * j + 1]);
        __nv_bfloat162 h = __float22bfloat162_rn(p);
        hi[j] = *(uint32_t*)&h;
        float2 rres = make_float2(p.x - __bfloat162float(h.x),
                                  p.y - __bfloat162float(h.y));
        __nv_bfloat162 l = __float22bfloat162_rn(rres);
        lo[j] = *(uint32_t*)&l;
    }
}

// ---------------- kernel 1: fused prep + HMMA GEMM + epilogue ----------------
__global__ void __launch_bounds__(TPB, 1)
main_kernel(const float* __restrict__ xb_g, const float* __restrict__ yb,
            const float* __restrict__ xq_g, const float* __restrict__ r,
            const float* __restrict__ sigma, const float* __restrict__ rscale,
            const float* __restrict__ w) {
    extern __shared__ char smem[];
    const uint32_t sbase = smem_u32(smem);
    const int tid = threadIdx.x, wid = tid >> 5, lane = tid & 31;
    const int q0 = blockIdx.x * QPC;
    const int b0 = blockIdx.y * BPC;
    const int qw = wid * 16;               // this warp's query offset within CTA
    const int part = tid & 3;              // quarter-row segment

    const float c1 = -LOG2E / __ldg(sigma);
    const float c2 = __ldg(rscale) * LOG2E;

    // ---- in-CTA prep: scale rows by w, split bf16, write SMEM tiles ----
    float wreg[8];
    *(float4*)(wreg)     = __ldg((const float4*)(w + part * 8));
    *(float4*)(wreg + 4) = __ldg((const float4*)(w + part * 8 + 4));

    float* q2s = (float*)(smem + SM_Q2);
    float* b2s = (float*)(smem + SM_B2);

    // A (queries): layout [hi | lo | hi]
#pragma unroll
    for (int i = 0; i < 2; ++i) {
        int ch = tid + i * TPB, row = ch >> 2;
        float v[8];
        *(float4*)(v)     = __ldg((const float4*)(xq_g + (size_t)(q0 + row) * DIM + part * 8));
        *(float4*)(v + 4) = __ldg((const float4*)(xq_g + (size_t)(q0 + row) * DIM + part * 8 + 4));
        float s = 0.f;
#pragma unroll
        for (int j = 0; j < 8; ++j) { v[j] *= wreg[j]; s = fmaf(v[j], v[j], s); }
        uint32_t hi[4], lo[4];
        cvt8(v, hi, lo);
        char* base = smem + SM_A + row * STRIDE + part * 16;
        *(uint4*)(base)       = make_uint4(hi[0], hi[1], hi[2], hi[3]);
        *(uint4*)(base + 64)  = make_uint4(lo[0], lo[1], lo[2], lo[3]);
        *(uint4*)(base + 128) = make_uint4(hi[0], hi[1], hi[2], hi[3]);
        s += __shfl_xor_sync(0xffffffffu, s, 1);
        s += __shfl_xor_sync(0xffffffffu, s, 2);
        if (part == 0) q2s[row] = s;
    }
    // B (backgrounds): layout [hi | hi | lo]
#pragma unroll
    for (int i = 0; i < 4; ++i) {
        int ch = tid + i * TPB, row = ch >> 2;
        float v[8];
        *(float4*)(v)     = __ldg((const float4*)(xb_g + (size_t)(b0 + row) * DIM + part * 8));
        *(float4*)(v + 4) = __ldg((const float4*)(xb_g + (size_t)(b0 + row) * DIM + part * 8 + 4));
        float s = 0.f;
#pragma unroll
        for (int j = 0; j < 8; ++j) { v[j] *= wreg[j]; s = fmaf(v[j], v[j], s); }
        uint32_t hi[4], lo[4];
        cvt8(v, hi, lo);
        char* base = smem + SM_B + row * STRIDE + part * 16;
        *(uint4*)(base)       = make_uint4(hi[0], hi[1], hi[2], hi[3]);
        *(uint4*)(base + 64)  = make_uint4(hi[0], hi[1], hi[2], hi[3]);
        *(uint4*)(base + 128) = make_uint4(lo[0], lo[1], lo[2], lo[3]);
        s += __shfl_xor_sync(0xffffffffu, s, 1);
        s += __shfl_xor_sync(0xffffffffu, s, 2);
        if (part == 0) b2s[row] = s;
    }
    if (tid < 128)
        *(float4*)(smem + SM_YB + tid * 16) = __ldg((const float4*)(yb + b0) + tid);
    __syncthreads();

    // ---- A fragments (register resident): 6 k-chunks x 4 regs (16 q rows) ----
    uint32_t afr[6][4];
    {
        int arow = (lane & 7) + ((lane >> 3) & 1) * 8;
        int akof = (lane >> 4) * 16;
#pragma unroll
        for (int c = 0; c < 6; ++c)
            ldsm_x4(afr[c], sbase + SM_A + (qw + arow) * STRIDE + c * 32 + akof);
    }
    // B ldsm.x4 lane address
    const int lg = lane >> 3;
    const int bsub = ((lg >> 1) << 3) + (lane & 7);
    const int bkh  = (lg & 1) << 4;
    const uint32_t bA = sbase + SM_B + bsub * STRIDE + bkh;       // n-tiles 0,1
    const uint32_t bB = bA + 16 * STRIDE;                          // n-tiles 2,3

    float* db = (float*)(smem + SM_DOT + wid * DOTSZ);
    const float* ybs = (const float*)(smem + SM_YB);
    const float q2a = q2s[qw + (lane >> 2)];
    const float q2b = q2s[qw + (lane >> 2) + 8];
    const float* rwarp = r + (size_t)(q0 + qw) * NB + b0;

    float aK[16], aY[16];
#pragma unroll
    for (int i = 0; i < 16; ++i) { aK[i] = 0.f; aY[i] = 0.f; }

    for (int s = 0; s < NGRP; ++s) {
        // hoist this group's r loads (coalesced; DRAM latency hidden by MMA)
        float rv[16];
        const float* rg = rwarp + s * GW + lane;
#pragma unroll
        for (int i = 0; i < 16; ++i) rv[i] = __ldcs(rg + (size_t)i * NB);

        // ---- MMA: 32 b x 16 q per warp ----
        float acc[4][4];
#pragma unroll
        for (int nt = 0; nt < 4; ++nt)
#pragma unroll
            for (int k = 0; k < 4; ++k) acc[nt][k] = 0.f;
#pragma unroll
        for (int c = 0; c < 6; ++c) {
            uint32_t b01[4], b23[4];
            ldsm_x4(b01, bA + s * (GW * STRIDE) + c * 32);
            ldsm_x4(b23, bB + s * (GW * STRIDE) + c * 32);
            mma_bf16(acc[0], afr[c], b01 + 0);
            mma_bf16(acc[1], afr[c], b01 + 2);
            mma_bf16(acc[2], afr[c], b23 + 0);
            mma_bf16(acc[3], afr[c], b23 + 2);
        }

        // ---- STS dots with q2 - 2*dot folded in ----
        {
            int row = (lane >> 2), col = (lane & 3) * 2;
#pragma unroll
            for (int nt = 0; nt < 4; ++nt) {
                *(float2*)(db + row * DSTR + nt * 8 + col) =
                    make_float2(fmaf(-2.f, acc[nt][0], q2a), fmaf(-2.f, acc[nt][1], q2a));
                *(float2*)(db + (row + 8) * DSTR + nt * 8 + col) =
                    make_float2(fmaf(-2.f, acc[nt][2], q2b), fmaf(-2.f, acc[nt][3], q2b));
            }
        }
        __syncwarp();

        // ---- epilogue: lane = b column; accumulate per-lane (no shuffles) ----
        const float b2v = b2s[s * GW + lane];
        const float ybv = ybs[s * GW + lane];
#pragma unroll
        for (int i = 0; i < 16; ++i) {
            float td = db[i * DSTR + lane];
            float d2 = fmaxf(td + b2v, 0.f);
            float d  = sqrta(d2);
            float kv = ex2a(fmaf(d, c1, rv[i] * c2));
            aK[i] += kv;
            aY[i] = fmaf(kv, ybv, aY[i]);
        }
        __syncwarp();
    }

    // ---- one-time transpose reduction over lanes ----
    float sk = treduce16(aK, lane);
    float sy = treduce16(aY, lane);
    if (!(lane & 1)) {
        int q = q0 + qw + (lane >> 1);
        g_pk [q * BSPL + blockIdx.y] = sk;
        g_pky[q * BSPL + blockIdx.y] = sy;
    }
}

// ---------------- kernel 2: finalize ----------------
__global__ void fin_kernel(float* __restrict__ out) {
    int q = blockIdx.x * blockDim.x + threadIdx.x;
    if (q >= NQ) return;
    float skv = 0.f, syv = 0.f;
#pragma unroll
    for (int s = 0; s < BSPL; ++s) {
        skv += g_pk [q * BSPL + s];
        syv += g_pky[q * BSPL + s];
    }
    out[q] = syv / (skv + 1e-8f);
}

extern "C" void kernel_launch(void* const* d_in, const int* in_sizes, int n_in,
                              void* d_out, int out_size) {
    const float* xb     = (const float*)d_in[0];
    const float* yb     = (const float*)d_in[1];
    const float* xq     = (const float*)d_in[2];
    const float* r      = (const float*)d_in[3];
    const float* sigma  = (const float*)d_in[4];
    const float* rscale = (const float*)d_in[5];
    const float* w      = (const float*)d_in[6];
    float* out = (float*)d_out;

    cudaFuncSetAttribute(main_kernel, cudaFuncAttributeMaxDynamicSharedMemorySize, SMEM_TOTAL);

    dim3 grid(NQ / QPC, BSPL);
    main_kernel<<<grid, TPB, SMEM_TOTAL>>>(xb, yb, xq, r, sigma, rscale, w);
    fin_kernel<<<(NQ + 255) / 256, 256>>>(out);
}

// round 7
// speedup vs baseline: 4.1959x; 1.0468x over previous
#include <cuda_runtime.h>
#include <cuda_bf16.h>
#include <cstdint>

#define NQ 2048
#define NB 8192
#define DIM 32
#define TPB 512
#define QPC 256            // queries per CTA
#define BSPL 16            // background splits (grid.y)
#define BPC (NB / BSPL)    // 512 backgrounds per CTA
#define GW  32             // group width in b
#define NGRP (BPC / GW)    // 16 groups
#define STRIDE 144         // SMEM row stride bytes: 128B data + pad (odd*16 -> ldsm conflict-free)
#define DSTR 40            // dot buffer stride (floats)
#define LOG2E 1.4426950408889634f

// ---------------- device scratch ----------------
__device__ float g_pk [NQ * BSPL];
__device__ float g_pky[NQ * BSPL];
__device__ int   g_cnt[NQ / QPC];      // arrival counters (zero-init, self-resetting)

// ---------------- helpers ----------------
__device__ __forceinline__ uint32_t smem_u32(const void* p) {
    uint32_t a;
    asm("{ .reg .u64 t; cvta.to.shared.u64 t, %1; cvt.u32.u64 %0, t; }" : "=r"(a) : "l"(p));
    return a;
}
__device__ __forceinline__ void ldsm_x4(uint32_t* r, uint32_t addr) {
    asm volatile("ldmatrix.sync.aligned.m8n8.x4.shared.b16 {%0,%1,%2,%3}, [%4];"
                 : "=r"(r[0]), "=r"(r[1]), "=r"(r[2]), "=r"(r[3]) : "r"(addr));
}
__device__ __forceinline__ void mma_bf16(float* d, const uint32_t* a, const uint32_t* b) {
    asm volatile(
        "mma.sync.aligned.m16n8k16.row.col.f32.bf16.bf16.f32 "
        "{%0,%1,%2,%3}, {%4,%5,%6,%7}, {%8,%9}, {%0,%1,%2,%3};"
        : "+f"(d[0]), "+f"(d[1]), "+f"(d[2]), "+f"(d[3])
        : "r"(a[0]), "r"(a[1]), "r"(a[2]), "r"(a[3]), "r"(b[0]), "r"(b[1]));
}
__device__ __forceinline__ float ex2a(float x) {
    float y; asm("ex2.approx.ftz.f32 %0, %1;" : "=f"(y) : "f"(x)); return y;
}
__device__ __forceinline__ float sqrta(float x) {
    float y; asm("sqrt.approx.f32 %0, %1;" : "=f"(y) : "f"(x)); return y;
}

// transpose-reduce 16 regs over 32 lanes; lane L ends holding total for idx (L>>1)&15
__device__ __forceinline__ float treduce16(float* v, int lane) {
#pragma unroll
    for (int o = 16; o >= 2; o >>= 1) {
        bool up = (lane & o) != 0;
#pragma unroll
        for (int j = 0; j < 16; ++j) {
            if (j < (o >> 1)) {
                float send = up ? v[j] : v[j + (o >> 1)];
                float recv = __shfl_xor_sync(0xffffffffu, send, o);
                float keep = up ? v[j + (o >> 1)] : v[j];
                v[j] = keep + recv;
            }
        }
    }
    return v[0] + __shfl_xor_sync(0xffffffffu, v[0], 1);
}

// ---------------- SMEM layout ----------------
#define SM_A   0                               // 256*144 = 36864
#define SM_B   36864                           // 512*144 = 73728
#define SM_DOT 110592                          // 16 warps * 2560
#define DOTSZ  (16 * DSTR * 4)
#define SM_B2  151552                          // 2048
#define SM_YB  153600                          // 2048
#define SM_Q2  155648                          // 1024
#define SMEM_TOTAL 156672

// convert 8 floats to hi/lo bf16 packs (4 uint32 each)
__device__ __forceinline__ void cvt8(const float* v, uint32_t* hi, uint32_t* lo) {
#pragma unroll
    for (int j = 0; j < 4; ++j) {
        float2 p = make_float2(v[2 * j], v[2 * j + 1]);
        __nv_bfloat162 h = __float22bfloat162_rn(p);
        hi[j] = *(uint32_t*)&h;
        float2 rres = make_float2(p.x - __bfloat162float(h.x),
                                  p.y - __bfloat162float(h.y));
        __nv_bfloat162 l = __float22bfloat162_rn(rres);
        lo[j] = *(uint32_t*)&l;
    }
}

// ---------------- fused kernel: prep + HMMA GEMM + epilogue + finalize ----------------
__global__ void __launch_bounds__(TPB, 1)
main_kernel(const float* __restrict__ xb_g, const float* __restrict__ yb,
            const float* __restrict__ xq_g, const float* __restrict__ r,
            const float* __restrict__ sigma, const float* __restrict__ rscale,
            const float* __restrict__ w, float* __restrict__ out) {
    extern __shared__ char smem[];
    __shared__ int is_last;
    const uint32_t sbase = smem_u32(smem);
    const int tid = threadIdx.x, wid = tid >> 5, lane = tid & 31;
    const int q0 = blockIdx.x * QPC;
    const int b0 = blockIdx.y * BPC;
    const int qw = wid * 16;
    const int part = tid & 3;

    const float c1 = -LOG2E / __ldg(sigma);
    const float c2 = __ldg(rscale) * LOG2E;

    // ---- in-CTA prep: scale by w, split bf16 [hi|lo], write SMEM tiles ----
    float wreg[8];
    *(float4*)(wreg)     = __ldg((const float4*)(w + part * 8));
    *(float4*)(wreg + 4) = __ldg((const float4*)(w + part * 8 + 4));

    float* q2s = (float*)(smem + SM_Q2);
    float* b2s = (float*)(smem + SM_B2);

#pragma unroll
    for (int i = 0; i < 2; ++i) {              // A (queries)
        int ch = tid + i * TPB, row = ch >> 2;
        float v[8];
        *(float4*)(v)     = __ldg((const float4*)(xq_g + (size_t)(q0 + row) * DIM + part * 8));
        *(float4*)(v + 4) = __ldg((const float4*)(xq_g + (size_t)(q0 + row) * DIM + part * 8 + 4));
        float s = 0.f;
#pragma unroll
        for (int j = 0; j < 8; ++j) { v[j] *= wreg[j]; s = fmaf(v[j], v[j], s); }
        uint32_t hi[4], lo[4];
        cvt8(v, hi, lo);
        char* base = smem + SM_A + row * STRIDE + part * 16;
        *(uint4*)(base)      = make_uint4(hi[0], hi[1], hi[2], hi[3]);
        *(uint4*)(base + 64) = make_uint4(lo[0], lo[1], lo[2], lo[3]);
        s += __shfl_xor_sync(0xffffffffu, s, 1);
        s += __shfl_xor_sync(0xffffffffu, s, 2);
        if (part == 0) q2s[row] = s;
    }
#pragma unroll
    for (int i = 0; i < 4; ++i) {              // B (backgrounds)
        int ch = tid + i * TPB, row = ch >> 2;
        float v[8];
        *(float4*)(v)     = __ldg((const float4*)(xb_g + (size_t)(b0 + row) * DIM + part * 8));
        *(float4*)(v + 4) = __ldg((const float4*)(xb_g + (size_t)(b0 + row) * DIM + part * 8 + 4));
        float s = 0.f;
#pragma unroll
        for (int j = 0; j < 8; ++j) { v[j] *= wreg[j]; s = fmaf(v[j], v[j], s); }
        uint32_t hi[4], lo[4];
        cvt8(v, hi, lo);
        char* base = smem + SM_B + row * STRIDE + part * 16;
        *(uint4*)(base)      = make_uint4(hi[0], hi[1], hi[2], hi[3]);
        *(uint4*)(base + 64) = make_uint4(lo[0], lo[1], lo[2], lo[3]);
        s += __shfl_xor_sync(0xffffffffu, s, 1);
        s += __shfl_xor_sync(0xffffffffu, s, 2);
        if (part == 0) b2s[row] = s;
    }
    if (tid < 128)
        *(float4*)(smem + SM_YB + tid * 16) = __ldg((const float4*)(yb + b0) + tid);
    __syncthreads();

    // ---- A fragments: 4 k-chunks (hi0,hi1,lo0,lo1) x 4 regs ----
    uint32_t afr[4][4];
    {
        int arow = (lane & 7) + ((lane >> 3) & 1) * 8;
        int akof = (lane >> 4) * 16;
#pragma unroll
        for (int c = 0; c < 4; ++c)
            ldsm_x4(afr[c], sbase + SM_A + (qw + arow) * STRIDE + c * 32 + akof);
    }
    const int lg = lane >> 3;
    const int bsub = ((lg >> 1) << 3) + (lane & 7);
    const int bkh  = (lg & 1) << 4;
    const uint32_t bA = sbase + SM_B + bsub * STRIDE + bkh;       // b rows 0-15  (nt0,nt1)
    const uint32_t bB = bA + 16 * STRIDE;                          // b rows 16-31 (nt2,nt3)

    float* db = (float*)(smem + SM_DOT + wid * DOTSZ);
    const float* ybs = (const float*)(smem + SM_YB);
    const float q2a = q2s[qw + (lane >> 2)];
    const float q2b = q2s[qw + (lane >> 2) + 8];
    const float* rwarp = r + (size_t)(q0 + qw) * NB + b0 + lane;

    float aK[16], aY[16];
#pragma unroll
    for (int i = 0; i < 16; ++i) { aK[i] = 0.f; aY[i] = 0.f; }

    float rv[2][16];
#pragma unroll
    for (int i = 0; i < 16; ++i) rv[0][i] = __ldcs(rwarp + (size_t)i * NB);

#pragma unroll 2
    for (int s = 0; s < NGRP; ++s) {
        const int cur = s & 1, nxt = cur ^ 1;

        // prefetch next group's r (consumed one full group later)
        if (s + 1 < NGRP) {
            const float* rg = rwarp + (s + 1) * GW;
#pragma unroll
            for (int i = 0; i < 16; ++i) rv[nxt][i] = __ldcs(rg + (size_t)i * NB);
        }

        // ---- MMA: 32 b x 16 q; hi/lo fragment pairing (6 k-step pairs) ----
        float acc[4][4];
#pragma unroll
        for (int nt = 0; nt < 4; ++nt)
#pragma unroll
            for (int k = 0; k < 4; ++k) acc[nt][k] = 0.f;
        {
            uint32_t bf01[4][4], bf23[4][4];
#pragma unroll
            for (int c = 0; c < 4; ++c) {
                ldsm_x4(bf01[c], bA + s * (GW * STRIDE) + c * 32);
                ldsm_x4(bf23[c], bB + s * (GW * STRIDE) + c * 32);
            }
            const int pa[6] = {0, 1, 2, 3, 0, 1};
            const int pb[6] = {0, 1, 0, 1, 2, 3};
#pragma unroll
            for (int p = 0; p < 6; ++p) {
                mma_bf16(acc[0], afr[pa[p]], bf01[pb[p]] + 0);
                mma_bf16(acc[1], afr[pa[p]], bf01[pb[p]] + 2);
                mma_bf16(acc[2], afr[pa[p]], bf23[pb[p]] + 0);
                mma_bf16(acc[3], afr[pa[p]], bf23[pb[p]] + 2);
            }
        }

        // ---- STS dots with q2 - 2*dot folded in ----
        {
            int row = (lane >> 2), col = (lane & 3) * 2;
#pragma unroll
            for (int nt = 0; nt < 4; ++nt) {
                *(float2*)(db + row * DSTR + nt * 8 + col) =
                    make_float2(fmaf(-2.f, acc[nt][0], q2a), fmaf(-2.f, acc[nt][1], q2a));
                *(float2*)(db + (row + 8) * DSTR + nt * 8 + col) =
                    make_float2(fmaf(-2.f, acc[nt][2], q2b), fmaf(-2.f, acc[nt][3], q2b));
            }
        }
        __syncwarp();

        // ---- epilogue: lane = b column; per-lane accumulation ----
        const float b2v = b2s[s * GW + lane];
        const float ybv = ybs[s * GW + lane];
#pragma unroll
        for (int i = 0; i < 16; ++i) {
            float td = db[i * DSTR + lane];
            float d2 = fmaxf(td + b2v, 0.f);
            float d  = sqrta(d2);
            float kv = ex2a(fmaf(d, c1, rv[cur][i] * c2));
            aK[i] += kv;
            aY[i] = fmaf(kv, ybv, aY[i]);
        }
        __syncwarp();
    }

    // ---- one-time transpose reduction, write partials ----
    float sk = treduce16(aK, lane);
    float sy = treduce16(aY, lane);
    if (!(lane & 1)) {
        int q = q0 + qw + (lane >> 1);
        g_pk [q * BSPL + blockIdx.y] = sk;
        g_pky[q * BSPL + blockIdx.y] = sy;
    }

    // ---- fused finalize: last split-CTA per q-chunk combines + normalizes ----
    __threadfence();
    __syncthreads();
    if (tid == 0)
        is_last = (atomicAdd(&g_cnt[blockIdx.x], 1) == BSPL - 1);
    __syncthreads();
    if (is_last) {
        if (tid < QPC) {
            int q = q0 + tid;
            float skv = 0.f, syv = 0.f;
#pragma unroll
            for (int s = 0; s < BSPL; ++s) {
                skv += __ldcg(&g_pk [q * BSPL + s]);
                syv += __ldcg(&g_pky[q * BSPL + s]);
            }
            out[q] = syv / (skv + 1e-8f);
        }
        if (tid == 0) g_cnt[blockIdx.x] = 0;   // self-reset for next replay
    }
}

extern "C" void kernel_launch(void* const* d_in, const int* in_sizes, int n_in,
                              void* d_out, int out_size) {
    const float* xb     = (const float*)d_in[0];
    const float* yb     = (const float*)d_in[1];
    const float* xq     = (const float*)d_in[2];
    const float* r      = (const float*)d_in[3];
    const float* sigma  = (const float*)d_in[4];
    const float* rscale = (const float*)d_in[5];
    const float* w      = (const float*)d_in[6];
    float* out = (float*)d_out;

    cudaFuncSetAttribute(main_kernel, cudaFuncAttributeMaxDynamicSharedMemorySize, SMEM_TOTAL);

    dim3 grid(NQ / QPC, BSPL);
    main_kernel<<<grid, TPB, SMEM_TOTAL>>>(xb, yb, xq, r, sigma, rscale, w, out);
}